// round 8
// baseline (speedup 1.0000x reference)
#include <cuda_runtime.h>

#define NN 4
#define BPTS 8192
#define CIN 32
#define DOUT 32
#define ANB 32
#define NBAS 36
#define TOTAL 32768
#define PPI 32
#define THREADS 512
#define WARPS 16
#define NITER (TOTAL/PPI)
#define KK 1152
#define KPW 72
#define MPS 33

typedef unsigned long long u64;

__device__ float g_inputT[NN*BPTS*CIN];   // (n,b,c)
__device__ float g_wlin[KK*32];           // [kk][d], kk=(s*4+r)*32+c

// ---------------- f32x2 helpers ----------------
__device__ __forceinline__ u64 pack2(float x, float y){
    u64 r; asm("mov.b64 %0,{%1,%2};" : "=l"(r) : "f"(x), "f"(y)); return r;
}
__device__ __forceinline__ void unpack2(u64 v, float& x, float& y){
    asm("mov.b64 {%0,%1},%2;" : "=f"(x), "=f"(y) : "l"(v));
}
__device__ __forceinline__ u64 fma2(u64 a, u64 b, u64 c){
    u64 d; asm("fma.rn.f32x2 %0,%1,%2,%3;" : "=l"(d) : "l"(a), "l"(b), "l"(c)); return d;
}
__device__ __forceinline__ u64 add2(u64 a, u64 b){
    u64 d; asm("add.rn.f32x2 %0,%1,%2;" : "=l"(d) : "l"(a), "l"(b)); return d;
}
__device__ __forceinline__ u64 mul2(u64 a, u64 b){
    u64 d; asm("mul.rn.f32x2 %0,%1,%2;" : "=l"(d) : "l"(a), "l"(b)); return d;
}
__device__ __forceinline__ float lds32(const float* p){
    float v; unsigned s = (unsigned)__cvta_generic_to_shared(p);
    asm volatile("ld.shared.f32 %0,[%1];" : "=f"(v) : "r"(s)); return v;
}
__device__ __forceinline__ void sts32(float* p, float v){
    unsigned s = (unsigned)__cvta_generic_to_shared(p);
    asm volatile("st.shared.f32 [%0],%1;" :: "r"(s), "f"(v));
}
__device__ __forceinline__ u64 lds64(const void* p){
    u64 v; unsigned s = (unsigned)__cvta_generic_to_shared(p);
    asm volatile("ld.shared.b64 %0,[%1];" : "=l"(v) : "r"(s)); return v;
}
__device__ __forceinline__ void sts64(void* p, u64 v){
    unsigned s = (unsigned)__cvta_generic_to_shared(p);
    asm volatile("st.shared.b64 [%0],%1;" :: "r"(s), "l"(v));
}

// ---------------- fused prep ----------------
__global__ void prep_all(const float* __restrict__ in, const float* __restrict__ W){
    const int bx = blockIdx.x;
    const int tid = threadIdx.x;           // 256
    if (bx < 1024){
        __shared__ float t[32][33];
        const int n  = bx >> 8;
        const int b0 = (bx & 255) * 32;
        const int tx = tid & 31, ty = tid >> 5;
        #pragma unroll
        for (int i = ty; i < 32; i += 8)
            t[i][tx] = in[(n*CIN + i)*BPTS + b0 + tx];
        __syncthreads();
        #pragma unroll
        for (int i = ty; i < 32; i += 8)
            g_inputT[(n*BPTS + b0 + i)*CIN + tx] = t[tx][i];
    } else {
        int t = (bx - 1024)*256 + tid;
        if (t < KK*32){
            int d  = t & 31;
            int kk = t >> 5;
            int c   = kk & 31;
            int s4r = kk >> 5;
            int r = s4r & 3, s = s4r >> 2;
            g_wlin[t] = W[(d*CIN + c)*NBAS + r*9 + s];
        }
    }
}

// ---------------- main ----------------
// smem:
//   geomP : 9 u64 fields x 512 rows  = 36864 B
//           fields: 0..3 = (rb_r,rb_r) dup; 4..7 = (y0,y1)(y2,y3)(y4,y5)(y6,y7); 8 = (y8,y8)
//   Mp    : KK*33 floats             = 152064 B
// total 188928 B. redd (16w*32l*17 u64 = 69632 B) ALIASES Mp (barrier-ordered).
#define SM_GP   0
#define SM_MP   (9*512*2)                 // in floats: 9216
#define SM_FLOATS (SM_MP + KK*MPS)

__global__ void __launch_bounds__(THREADS, 1)
se3_main(const float* __restrict__ coords,
         const float* __restrict__ rmask,
         const int*   __restrict__ nbrs,
         float*       __restrict__ out)
{
    extern __shared__ float smem[];
    u64*   geomP = (u64*)(smem + SM_GP);     // [q*512 + row]
    float* Mp    = smem + SM_MP;             // [kk*33 + p]
    u64*   redd  = (u64*)Mp;                 // alias, barrier-ordered

    const int tid  = threadIdx.x;
    const int w    = tid >> 5;               // 0..15
    const int lane = tid & 31;
    const int pg   = lane & 7;               // p-chunk (4 p each)
    const int dg   = lane >> 3;              // d-group (8 d each)

    for (int grp = blockIdx.x; grp < NITER; grp += gridDim.x) {
        const int flatbase = grp*PPI;
        const int n   = flatbase >> 13;
        const int bb0 = flatbase & (BPTS-1);

        // ================= Phase A: 2 points per warp =================
        #pragma unroll 1
        for (int sub = 0; sub < 2; sub++){
            const int p = w*2 + sub;
            const int flat = flatbase + p;

            // geometry, lane = neighbor a
            const int nb_idx = flat*ANB + lane;
            const int jn  = nbrs[nb_idx];
            const float msk = rmask[nb_idx];
            const float* cc = coords + (long)flat*3;
            const float c0x = cc[0], c0y = cc[1], c0z = cc[2];
            const float* cj = coords + ((long)(n*BPTS + jn))*3;
            const float dx = cj[0]-c0x, dy = cj[1]-c0y, dz = cj[2]-c0z;
            const float r  = sqrtf(dx*dx + dy*dy + dz*dz);
            const float inv = __fdividef(1.0f, r + 1e-8f);
            const float ux = dx*inv, uy = dy*inv, uz = dz*inv;
            const float y0 = 0.28209479f;
            const float y1 = 0.48860251f*ux, y2 = 0.48860251f*uy, y3 = 0.48860251f*uz;
            const float y4 = 1.09254843f*ux*uy, y5 = 1.09254843f*uy*uz;
            const float y6 = 0.31539157f*(3.0f*uz*uz - 1.0f);
            const float y7 = 1.09254843f*ux*uz;
            const float y8 = 0.54627421f*(ux*ux - uy*uy);
            float rb0, rb1, rb2, rb3;
            {
                float t0 = (r - 0.5f)*2.0f, t1 = (r - 1.0f)*2.0f;
                float t2 = (r - 1.5f)*2.0f, t3 = (r - 2.0f)*2.0f;
                rb0 = msk*__expf(-t0*t0); rb1 = msk*__expf(-t1*t1);
                rb2 = msk*__expf(-t2*t2); rb3 = msk*__expf(-t3*t3);
            }
            // SoA fields, lane-distinct stride-1 => conflict-free sts64
            const int row = w*32 + lane;
            sts64(geomP + 0*512 + row, pack2(rb0, rb0));
            sts64(geomP + 1*512 + row, pack2(rb1, rb1));
            sts64(geomP + 2*512 + row, pack2(rb2, rb2));
            sts64(geomP + 3*512 + row, pack2(rb3, rb3));
            sts64(geomP + 4*512 + row, pack2(y0, y1));
            sts64(geomP + 5*512 + row, pack2(y2, y3));
            sts64(geomP + 6*512 + row, pack2(y4, y5));
            sts64(geomP + 7*512 + row, pack2(y6, y7));
            sts64(geomP + 8*512 + row, pack2(y8, y8));
            __syncwarp();

            // feature gather (lane = channel c), prefetch depth 8
            const float* inrow = g_inputT + (((long)n << 13) * CIN) + lane;
            float fp[8];
            #pragma unroll
            for (int q = 0; q < 8; q++){
                int jq = __shfl_sync(0xffffffffu, jn, q);
                fp[q] = __ldg(inrow + (long)jq*CIN);
            }
            // accumulators: M[r][j] = (M[s=2j][r], M[s=2j+1][r]); j=4 lo = M[s=8][r]
            u64 M[4][5];
            #pragma unroll
            for (int r4 = 0; r4 < 4; r4++)
                #pragma unroll
                for (int jj = 0; jj < 5; jj++) M[r4][jj] = 0ull;

            #pragma unroll
            for (int a8 = 0; a8 < 32; a8 += 8){
                #pragma unroll
                for (int q = 0; q < 8; q++){
                    const int a = a8 + q;
                    const int row2 = w*32 + a;
                    u64 yv0 = lds64(geomP + 4*512 + row2);
                    u64 yv1 = lds64(geomP + 5*512 + row2);
                    u64 yv2 = lds64(geomP + 6*512 + row2);
                    u64 yv3 = lds64(geomP + 7*512 + row2);
                    u64 yv4 = lds64(geomP + 8*512 + row2);
                    u64 rd0 = lds64(geomP + 0*512 + row2);
                    u64 rd1 = lds64(geomP + 1*512 + row2);
                    u64 rd2 = lds64(geomP + 2*512 + row2);
                    u64 rd3 = lds64(geomP + 3*512 + row2);
                    const float f = fp[q];
                    if (a8 + 8 < 32){
                        int jq = __shfl_sync(0xffffffffu, jn, a + 8);
                        fp[q] = __ldg(inrow + (long)jq*CIN);
                    }
                    u64 f2 = pack2(f, f);
                    u64 fr0 = mul2(f2, rd0);
                    u64 fr1 = mul2(f2, rd1);
                    u64 fr2 = mul2(f2, rd2);
                    u64 fr3 = mul2(f2, rd3);
                    M[0][0]=fma2(fr0,yv0,M[0][0]); M[0][1]=fma2(fr0,yv1,M[0][1]);
                    M[0][2]=fma2(fr0,yv2,M[0][2]); M[0][3]=fma2(fr0,yv3,M[0][3]);
                    M[0][4]=fma2(fr0,yv4,M[0][4]);
                    M[1][0]=fma2(fr1,yv0,M[1][0]); M[1][1]=fma2(fr1,yv1,M[1][1]);
                    M[1][2]=fma2(fr1,yv2,M[1][2]); M[1][3]=fma2(fr1,yv3,M[1][3]);
                    M[1][4]=fma2(fr1,yv4,M[1][4]);
                    M[2][0]=fma2(fr2,yv0,M[2][0]); M[2][1]=fma2(fr2,yv1,M[2][1]);
                    M[2][2]=fma2(fr2,yv2,M[2][2]); M[2][3]=fma2(fr2,yv3,M[2][3]);
                    M[2][4]=fma2(fr2,yv4,M[2][4]);
                    M[3][0]=fma2(fr3,yv0,M[3][0]); M[3][1]=fma2(fr3,yv1,M[3][1]);
                    M[3][2]=fma2(fr3,yv2,M[3][2]); M[3][3]=fma2(fr3,yv3,M[3][3]);
                    M[3][4]=fma2(fr3,yv4,M[3][4]);
                }
            }
            // Mp[kk][p], kk=(s*4+r)*32+c(=lane): conflict-free scalar stores
            #pragma unroll
            for (int r4 = 0; r4 < 4; r4++){
                #pragma unroll
                for (int jj = 0; jj < 4; jj++){
                    float alo, ahi;
                    unpack2(M[r4][jj], alo, ahi);
                    sts32(Mp + (((2*jj  )*4 + r4)*32 + lane)*MPS + p, alo);
                    sts32(Mp + (((2*jj+1)*4 + r4)*32 + lane)*MPS + p, ahi);
                }
                float alo, ahi;
                unpack2(M[r4][4], alo, ahi);
                sts32(Mp + ((8*4 + r4)*32 + lane)*MPS + p, alo);
            }
            __syncwarp();
        }
        __syncthreads();   // Mp complete

        // ================= Phase B: k-split GEMM, d-paired =================
        u64 acc[4][4];     // [pi][dd]  d-pair = (dg*8+dd*2, +1)
        #pragma unroll
        for (int a = 0; a < 4; a++)
            #pragma unroll
            for (int b = 0; b < 4; b++) acc[a][b] = 0ull;

        const int kb = w*KPW;
        const ulonglong2* wq = ((const ulonglong2*)g_wlin) + dg*2;  // + k*8 (+1)
        ulonglong2 pf0[3], pf1[3];
        #pragma unroll
        for (int i = 0; i < 3; i++){
            pf0[i] = __ldg(wq + (long)(kb+i)*8);
            pf1[i] = __ldg(wq + (long)(kb+i)*8 + 1);
        }
        #pragma unroll 3
        for (int kk = 0; kk < KPW; kk++){
            const int k = kb + kk;
            const int slot = kk % 3;
            const ulonglong2 wa = pf0[slot];
            const ulonglong2 wb = pf1[slot];
            if (kk + 3 < KPW){
                pf0[slot] = __ldg(wq + (long)(k+3)*8);
                pf1[slot] = __ldg(wq + (long)(k+3)*8 + 1);
            }
            const float* mr = Mp + k*MPS + pg*4;
            float m0 = lds32(mr+0), m1 = lds32(mr+1);
            float m2 = lds32(mr+2), m3 = lds32(mr+3);
            u64 md0 = pack2(m0,m0), md1 = pack2(m1,m1);
            u64 md2 = pack2(m2,m2), md3 = pack2(m3,m3);
            acc[0][0]=fma2(md0, wa.x, acc[0][0]);
            acc[0][1]=fma2(md0, wa.y, acc[0][1]);
            acc[0][2]=fma2(md0, wb.x, acc[0][2]);
            acc[0][3]=fma2(md0, wb.y, acc[0][3]);
            acc[1][0]=fma2(md1, wa.x, acc[1][0]);
            acc[1][1]=fma2(md1, wa.y, acc[1][1]);
            acc[1][2]=fma2(md1, wb.x, acc[1][2]);
            acc[1][3]=fma2(md1, wb.y, acc[1][3]);
            acc[2][0]=fma2(md2, wa.x, acc[2][0]);
            acc[2][1]=fma2(md2, wa.y, acc[2][1]);
            acc[2][2]=fma2(md2, wb.x, acc[2][2]);
            acc[2][3]=fma2(md2, wb.y, acc[2][3]);
            acc[3][0]=fma2(md3, wa.x, acc[3][0]);
            acc[3][1]=fma2(md3, wa.y, acc[3][1]);
            acc[3][2]=fma2(md3, wb.x, acc[3][2]);
            acc[3][3]=fma2(md3, wb.y, acc[3][3]);
        }
        __syncthreads();   // all Mp reads done before redd (alias) writes

        // partial store: per-thread slot, pad 17 u64 -> conflict-free
        {
            u64* slotp = redd + (u64)(w*32 + lane)*17;
            #pragma unroll
            for (int pi = 0; pi < 4; pi++)
                #pragma unroll
                for (int dd = 0; dd < 4; dd++)
                    sts64(slotp + pi*4 + dd, acc[pi][dd]);
        }
        __syncthreads();

        // reduce 16 k-slices
        {
            const int rw = tid >> 5;           // 0..15 = pi*4+dd
            const int rl = tid & 31;           // producer lane
            const int pi = rw >> 2, dd = rw & 3;
            const int dgp = rl >> 3, pgp = rl & 7;
            const u64* base = redd + rl*17 + rw;
            u64 s = lds64(base);
            #pragma unroll
            for (int ks = 1; ks < 16; ks++)
                s = add2(s, lds64(base + ks*544));
            float lo, hi; unpack2(s, lo, hi);
            const int p = pgp*4 + pi;
            const int d = dgp*8 + dd*2;
            float* o = out + ((long)(n*DOUT + d))*BPTS + bb0 + p;
            o[0]    = lo;
            o[BPTS] = hi;
        }
        __syncthreads();   // protect redd (=Mp) before next iter's Phase A
    }
}

// ---------------- launch ----------------
extern "C" void kernel_launch(void* const* d_in, const int* in_sizes, int n_in,
                              void* d_out, int out_size)
{
    const float* input  = (const float*)d_in[0];
    const float* coords = (const float*)d_in[1];
    const float* rmask  = (const float*)d_in[2];
    const float* W      = (const float*)d_in[3];
    const int*   nbrs   = (const int*)d_in[4];
    float* out = (float*)d_out;

    (void)in_sizes; (void)n_in; (void)out_size;

    prep_all<<<1168, 256>>>(input, W);

    int dev = 0; cudaGetDevice(&dev);
    int smcount = 148;
    cudaDeviceGetAttribute(&smcount, cudaDevAttrMultiProcessorCount, dev);

    size_t shmem = (size_t)SM_FLOATS * sizeof(float);   // 188928 B
    cudaFuncSetAttribute(se3_main, cudaFuncAttributeMaxDynamicSharedMemorySize, (int)shmem);
    se3_main<<<smcount, THREADS, shmem>>>(coords, rmask, nbrs, out);
}